// round 9
// baseline (speedup 1.0000x reference)
#include <cuda_runtime.h>
#include <cuda_fp16.h>

// SemiConv2d (tropical conv): out[n,oc,h,w] = max_{ic,kh,kw} min(xpad, K)
// x: (8,32,96,96) f32, K: (32,32,3,3) f32, out f32, pad=1 with -inf.
//
// Per-(oc,kw) sorted tap lists (descending k), processed as 3 phases with
// exact early exit per phase (remaining taps in a list have k <= min(acc);
// acc only grows, so skipping them is exact). kw is a compile-time constant
// per phase: kw=0/2 use pure register selection (zero PRMT), kw=1 uses
// constant-selector PRMT. Records are 64-bit: (k pre-splatted, byte offset).

#define N_      8
#define IC_     32
#define OC_     32
#define H_      96
#define W_      96
#define TILE_H  8
#define XROWS   10           // TILE_H + 2 halo rows
#define XS_STRIDE 104        // halves per row (208 B, 16B multiple)
#define OC_PER_BLK 8
#define THREADS 768
#define NTAPS   288
#define LTAPS   96           // taps per (oc, kw) list

__device__ uint2 g_taps[OC_ * 3 * LTAPS];   // [oc][kw][rank] = (k_splat, byte_off)

__global__ void semiconv2d_prep(const float* __restrict__ kern) {
    __shared__ __half kv[3][LTAPS];
    const int oc = blockIdx.x;
    const int t  = threadIdx.x;
    int ic = t / 9, rr = t % 9, kh = rr / 3, kw = rr % 3;
    int li = ic * 3 + kh;                       // index within kw-list
    __half me = __float2half_rn(kern[oc * NTAPS + t]);
    kv[kw][li] = me;
    __syncthreads();
    int rank = 0;
    #pragma unroll 4
    for (int j = 0; j < LTAPS; j++) {
        __half kj = kv[kw][j];
        rank += (__hgt(kj, me) || (__heq(kj, me) && j < li)) ? 1 : 0;
    }
    unsigned bits  = (unsigned)__half_as_ushort(me);
    unsigned kspl  = bits * 0x10001u;                           // (k, k)
    unsigned offb  = (unsigned)(((ic * XROWS + kh) * XS_STRIDE) * 2);  // bytes, 16B mult
    g_taps[(oc * 3 + kw) * LTAPS + rank] = make_uint2(kspl, offb);
}

__device__ __forceinline__ __half2 u2h2(unsigned u) { return *(__half2*)&u; }

__global__ __launch_bounds__(THREADS, 2)
void semiconv2d_3ph(const float* __restrict__ x,
                    float* __restrict__ out) {
    extern __shared__ __align__(16) char smraw[];
    __half* xs    = (__half*)smraw;                                 // [IC][XROWS][XS_STRIDE]
    uint2*  tapss = (uint2*)(smraw + (size_t)IC_ * XROWS * XS_STRIDE * sizeof(__half)); // [8][3][96]

    const int tid    = threadIdx.x;
    const int n      = blockIdx.z;
    const int ocbase = blockIdx.y * OC_PER_BLK;
    const int h0     = blockIdx.x * TILE_H;
    const float   NEGF = -__int_as_float(0x7f800000);
    const __half2 NEG2 = __half2half2(__ushort_as_half((unsigned short)0xFC00));

    // ---- fill x tile: half2 granularity (col p pairs), -inf halo ----
    const float* xn = x + (size_t)n * IC_ * H_ * W_;
    __half2* xsh2 = (__half2*)xs;
    const int NH2 = IC_ * XROWS * (XS_STRIDE / 2);   // 16640
    for (int t = tid; t < NH2; t += THREADS) {
        int row = t / (XS_STRIDE / 2);
        int c2  = t % (XS_STRIDE / 2);
        int ic  = row / XROWS;
        int r   = row % XROWS;
        int g   = h0 - 1 + r;
        int p0  = 2 * c2;                 // padded cols p0, p0+1 -> x cols p-1
        float a = NEGF, b = NEGF;
        if (g >= 0 && g < H_) {
            const float* xr = xn + (ic * H_ + g) * W_;
            if (p0 >= 1 && p0 <= W_)         a = xr[p0 - 1];
            if (p0 + 1 >= 1 && p0 + 1 <= W_) b = xr[p0];
        }
        xsh2[t] = __floats2half2_rn(a, b);
    }
    // ---- sorted tap lists for this block's 8 ocs (uint4 copy) ----
    {
        const uint4* src = (const uint4*)(g_taps + (size_t)ocbase * 3 * LTAPS);
        uint4*       dst = (uint4*)tapss;
        for (int e = tid; e < OC_PER_BLK * 3 * LTAPS / 2; e += THREADS)
            dst[e] = src[e];
    }
    __syncthreads();

    // thread -> (local oc, h row, 8-wide w strip); warp is oc-uniform
    const int ocl = tid / 96;
    const int s   = tid % 96;
    const int hl  = s / 12;
    const int w0  = (s % 12) * 8;
    const int h   = h0 + hl;

    __half2 acc0 = NEG2, acc1 = NEG2, acc2 = NEG2, acc3 = NEG2;

    const char*  xb = (const char*)(xs + hl * XS_STRIDE + w0);   // 16B aligned
    const uint2* tp = tapss + ocl * 3 * LTAPS;

    // ---------------- phase kw = 0 : cols w0..w0+7 = va.x..va.w ----------------
    #pragma unroll 1
    for (int i = 0; i < LTAPS; i += 4) {
        uint4 ra = *(const uint4*)(tp + i);
        uint4 rb = *(const uint4*)(tp + i + 2);
        __half2 m = __hmin2(__hmin2(acc0, acc1), __hmin2(acc2, acc3));
        if (__hbge2(m, u2h2(ra.x))) break;
        {
            uint4 va = *(const uint4*)(xb + ra.y); __half2 k = u2h2(ra.x);
            acc0 = __hmax2(acc0, __hmin2(u2h2(va.x), k));
            acc1 = __hmax2(acc1, __hmin2(u2h2(va.y), k));
            acc2 = __hmax2(acc2, __hmin2(u2h2(va.z), k));
            acc3 = __hmax2(acc3, __hmin2(u2h2(va.w), k));
        }
        {
            uint4 va = *(const uint4*)(xb + ra.w); __half2 k = u2h2(ra.z);
            acc0 = __hmax2(acc0, __hmin2(u2h2(va.x), k));
            acc1 = __hmax2(acc1, __hmin2(u2h2(va.y), k));
            acc2 = __hmax2(acc2, __hmin2(u2h2(va.z), k));
            acc3 = __hmax2(acc3, __hmin2(u2h2(va.w), k));
        }
        {
            uint4 va = *(const uint4*)(xb + rb.y); __half2 k = u2h2(rb.x);
            acc0 = __hmax2(acc0, __hmin2(u2h2(va.x), k));
            acc1 = __hmax2(acc1, __hmin2(u2h2(va.y), k));
            acc2 = __hmax2(acc2, __hmin2(u2h2(va.z), k));
            acc3 = __hmax2(acc3, __hmin2(u2h2(va.w), k));
        }
        {
            uint4 va = *(const uint4*)(xb + rb.w); __half2 k = u2h2(rb.z);
            acc0 = __hmax2(acc0, __hmin2(u2h2(va.x), k));
            acc1 = __hmax2(acc1, __hmin2(u2h2(va.y), k));
            acc2 = __hmax2(acc2, __hmin2(u2h2(va.z), k));
            acc3 = __hmax2(acc3, __hmin2(u2h2(va.w), k));
        }
    }

    // ---------------- phase kw = 1 : cols w0+1..w0+8 via PRMT 0x5432 ----------------
    #pragma unroll 1
    for (int i = 0; i < LTAPS; i += 4) {
        uint4 ra = *(const uint4*)(tp + LTAPS + i);
        uint4 rb = *(const uint4*)(tp + LTAPS + i + 2);
        __half2 m = __hmin2(__hmin2(acc0, acc1), __hmin2(acc2, acc3));
        if (__hbge2(m, u2h2(ra.x))) break;
        #pragma unroll
        for (int j = 0; j < 4; j++) {
            unsigned kk  = (j == 0) ? ra.x : (j == 1) ? ra.z : (j == 2) ? rb.x : rb.z;
            unsigned off = (j == 0) ? ra.y : (j == 1) ? ra.w : (j == 2) ? rb.y : rb.w;
            uint4 va = *(const uint4*)(xb + off);
            unsigned vb = *(const unsigned*)(xb + off + 16);
            unsigned x0 = __byte_perm(va.x, va.y, 0x5432);
            unsigned x1 = __byte_perm(va.y, va.z, 0x5432);
            unsigned x2 = __byte_perm(va.z, va.w, 0x5432);
            unsigned x3 = __byte_perm(va.w, vb,   0x5432);
            __half2 k = u2h2(kk);
            acc0 = __hmax2(acc0, __hmin2(u2h2(x0), k));
            acc1 = __hmax2(acc1, __hmin2(u2h2(x1), k));
            acc2 = __hmax2(acc2, __hmin2(u2h2(x2), k));
            acc3 = __hmax2(acc3, __hmin2(u2h2(x3), k));
        }
    }

    // ---------------- phase kw = 2 : cols w0+2..w0+9 = va.y..vb ----------------
    #pragma unroll 1
    for (int i = 0; i < LTAPS; i += 4) {
        uint4 ra = *(const uint4*)(tp + 2 * LTAPS + i);
        uint4 rb = *(const uint4*)(tp + 2 * LTAPS + i + 2);
        __half2 m = __hmin2(__hmin2(acc0, acc1), __hmin2(acc2, acc3));
        if (__hbge2(m, u2h2(ra.x))) break;
        #pragma unroll
        for (int j = 0; j < 4; j++) {
            unsigned kk  = (j == 0) ? ra.x : (j == 1) ? ra.z : (j == 2) ? rb.x : rb.z;
            unsigned off = (j == 0) ? ra.y : (j == 1) ? ra.w : (j == 2) ? rb.y : rb.w;
            uint4 va = *(const uint4*)(xb + off);
            unsigned vb = *(const unsigned*)(xb + off + 16);
            __half2 k = u2h2(kk);
            acc0 = __hmax2(acc0, __hmin2(u2h2(va.y), k));
            acc1 = __hmax2(acc1, __hmin2(u2h2(va.z), k));
            acc2 = __hmax2(acc2, __hmin2(u2h2(va.w), k));
            acc3 = __hmax2(acc3, __hmin2(u2h2(vb),   k));
        }
    }

    // ---- write 8 w outputs as f32 ----
    int oc = ocbase + ocl;
    float4* o = (float4*)(out + (((size_t)n * OC_ + oc) * H_ + h) * W_ + w0);
    float2 f0 = __half22float2(acc0);
    float2 f1 = __half22float2(acc1);
    float2 f2 = __half22float2(acc2);
    float2 f3 = __half22float2(acc3);
    o[0] = make_float4(f0.x, f0.y, f1.x, f1.y);
    o[1] = make_float4(f2.x, f2.y, f3.x, f3.y);
}

extern "C" void kernel_launch(void* const* d_in, const int* in_sizes, int n_in,
                              void* d_out, int out_size) {
    const float* x = (const float*)d_in[0];
    const float* k = (const float*)d_in[1];
    float* out = (float*)d_out;

    semiconv2d_prep<<<OC_, NTAPS>>>(k);

    size_t smem = (size_t)IC_ * XROWS * XS_STRIDE * sizeof(__half)
                + (size_t)OC_PER_BLK * 3 * LTAPS * sizeof(uint2);  // 66560 + 18432 = 84992 B
    cudaFuncSetAttribute(semiconv2d_3ph,
                         cudaFuncAttributeMaxDynamicSharedMemorySize, (int)smem);
    dim3 grid(H_ / TILE_H, OC_ / OC_PER_BLK, N_);                   // 12 x 4 x 8 = 384
    semiconv2d_3ph<<<grid, THREADS, smem>>>(x, out);
}

// round 10
// speedup vs baseline: 1.2581x; 1.2581x over previous
#include <cuda_runtime.h>
#include <cuda_fp16.h>

// SemiConv2d (tropical conv): out[n,oc,h,w] = max_{ic,kh,kw} min(xpad, K)
// x: (8,32,96,96) f32, K: (32,32,3,3) f32, out f32, pad=1 with -inf.
//
// Per-(oc,kw) sorted tap lists (descending k), processed ROUND-ROBIN:
// each iteration takes 2 taps from each kw-list and does ONE exact exit
// check against max(head0, head1, head2) (bounds every remaining tap).
// kw is compile-time constant per sub-body: kw=0/2 pure register select,
// kw=1 constant-selector PRMT. Records: (k pre-splatted, byte offset).

#define N_      8
#define IC_     32
#define OC_     32
#define H_      96
#define W_      96
#define TILE_H  8
#define XROWS   10           // TILE_H + 2 halo rows
#define XS_STRIDE 104        // halves per row (208 B, 16B multiple)
#define OC_PER_BLK 8
#define THREADS 768
#define NTAPS   288
#define LTAPS   96           // taps per (oc, kw) list

__device__ uint2 g_taps[OC_ * 3 * LTAPS];   // [oc][kw][rank] = (k_splat, byte_off)

__global__ void semiconv2d_prep(const float* __restrict__ kern) {
    __shared__ __half kv[3][LTAPS];
    const int oc = blockIdx.x;
    const int t  = threadIdx.x;
    int ic = t / 9, rr = t % 9, kh = rr / 3, kw = rr % 3;
    int li = ic * 3 + kh;
    __half me = __float2half_rn(kern[oc * NTAPS + t]);
    kv[kw][li] = me;
    __syncthreads();
    int rank = 0;
    #pragma unroll 4
    for (int j = 0; j < LTAPS; j++) {
        __half kj = kv[kw][j];
        rank += (__hgt(kj, me) || (__heq(kj, me) && j < li)) ? 1 : 0;
    }
    unsigned bits = (unsigned)__half_as_ushort(me);
    unsigned kspl = bits * 0x10001u;
    unsigned offb = (unsigned)(((ic * XROWS + kh) * XS_STRIDE) * 2);   // bytes
    g_taps[(oc * 3 + kw) * LTAPS + rank] = make_uint2(kspl, offb);
}

__device__ __forceinline__ __half2 u2h2(unsigned u) { return *(__half2*)&u; }

__global__ __launch_bounds__(THREADS, 2)
void semiconv2d_rr(const float* __restrict__ x,
                   float* __restrict__ out) {
    extern __shared__ __align__(16) char smraw[];
    __half* xs    = (__half*)smraw;                                 // [IC][XROWS][XS_STRIDE]
    uint2*  tapss = (uint2*)(smraw + (size_t)IC_ * XROWS * XS_STRIDE * sizeof(__half));

    const int tid    = threadIdx.x;
    const int n      = blockIdx.z;
    const int ocbase = blockIdx.y * OC_PER_BLK;
    const int h0     = blockIdx.x * TILE_H;
    const float   NEGF = -__int_as_float(0x7f800000);
    const __half2 NEG2 = __half2half2(__ushort_as_half((unsigned short)0xFC00));

    // ---- fill x tile (half2 granularity, -inf halo) ----
    const float* xn = x + (size_t)n * IC_ * H_ * W_;
    __half2* xsh2 = (__half2*)xs;
    const int NH2 = IC_ * XROWS * (XS_STRIDE / 2);
    for (int t = tid; t < NH2; t += THREADS) {
        int row = t / (XS_STRIDE / 2);
        int c2  = t % (XS_STRIDE / 2);
        int ic  = row / XROWS;
        int r   = row % XROWS;
        int g   = h0 - 1 + r;
        int p0  = 2 * c2;
        float a = NEGF, b = NEGF;
        if (g >= 0 && g < H_) {
            const float* xr = xn + (ic * H_ + g) * W_;
            if (p0 >= 1 && p0 <= W_)         a = xr[p0 - 1];
            if (p0 + 1 >= 1 && p0 + 1 <= W_) b = xr[p0];
        }
        xsh2[t] = __floats2half2_rn(a, b);
    }
    {
        const uint4* src = (const uint4*)(g_taps + (size_t)ocbase * 3 * LTAPS);
        uint4*       dst = (uint4*)tapss;
        for (int e = tid; e < OC_PER_BLK * 3 * LTAPS / 2; e += THREADS)
            dst[e] = src[e];
    }
    __syncthreads();

    // thread -> (local oc, h row, 8-wide w strip); warp is oc-uniform
    const int ocl = tid / 96;
    const int s   = tid % 96;
    const int hl  = s / 12;
    const int w0  = (s % 12) * 8;
    const int h   = h0 + hl;

    __half2 acc0 = NEG2, acc1 = NEG2, acc2 = NEG2, acc3 = NEG2;

    const char*  xb  = (const char*)(xs + hl * XS_STRIDE + w0);   // 16B aligned base
    const uint2* tp0 = tapss + ocl * 3 * LTAPS;
    const uint2* tp1 = tp0 + LTAPS;
    const uint2* tp2 = tp0 + 2 * LTAPS;

    #pragma unroll 1
    for (int i = 0; i < LTAPS; i += 2) {
        uint4 r0 = *(const uint4*)(tp0 + i);    // 2 recs, kw=0
        uint4 r1 = *(const uint4*)(tp1 + i);    // 2 recs, kw=1
        uint4 r2 = *(const uint4*)(tp2 + i);    // 2 recs, kw=2

        // exact exit: every remaining tap has k <= max of the 3 heads
        __half2 kmax = __hmax2(__hmax2(u2h2(r0.x), u2h2(r1.x)), u2h2(r2.x));
        __half2 m    = __hmin2(__hmin2(acc0, acc1), __hmin2(acc2, acc3));
        if (__hbge2(m, kmax)) break;

        // ---- kw = 0: cols w0..w0+7 = va.x..va.w ----
        {
            uint4 va = *(const uint4*)(xb + r0.y); __half2 k = u2h2(r0.x);
            acc0 = __hmax2(acc0, __hmin2(u2h2(va.x), k));
            acc1 = __hmax2(acc1, __hmin2(u2h2(va.y), k));
            acc2 = __hmax2(acc2, __hmin2(u2h2(va.z), k));
            acc3 = __hmax2(acc3, __hmin2(u2h2(va.w), k));
        }
        {
            uint4 va = *(const uint4*)(xb + r0.w); __half2 k = u2h2(r0.z);
            acc0 = __hmax2(acc0, __hmin2(u2h2(va.x), k));
            acc1 = __hmax2(acc1, __hmin2(u2h2(va.y), k));
            acc2 = __hmax2(acc2, __hmin2(u2h2(va.z), k));
            acc3 = __hmax2(acc3, __hmin2(u2h2(va.w), k));
        }
        // ---- kw = 1: cols w0+1..w0+8 via PRMT 0x5432 ----
        {
            uint4 va = *(const uint4*)(xb + r1.y);
            unsigned ve = *(const unsigned*)(xb + r1.y + 16);
            __half2 k = u2h2(r1.x);
            unsigned x0 = __byte_perm(va.x, va.y, 0x5432);
            unsigned x1 = __byte_perm(va.y, va.z, 0x5432);
            unsigned x2 = __byte_perm(va.z, va.w, 0x5432);
            unsigned x3 = __byte_perm(va.w, ve,   0x5432);
            acc0 = __hmax2(acc0, __hmin2(u2h2(x0), k));
            acc1 = __hmax2(acc1, __hmin2(u2h2(x1), k));
            acc2 = __hmax2(acc2, __hmin2(u2h2(x2), k));
            acc3 = __hmax2(acc3, __hmin2(u2h2(x3), k));
        }
        {
            uint4 va = *(const uint4*)(xb + r1.w);
            unsigned ve = *(const unsigned*)(xb + r1.w + 16);
            __half2 k = u2h2(r1.z);
            unsigned x0 = __byte_perm(va.x, va.y, 0x5432);
            unsigned x1 = __byte_perm(va.y, va.z, 0x5432);
            unsigned x2 = __byte_perm(va.z, va.w, 0x5432);
            unsigned x3 = __byte_perm(va.w, ve,   0x5432);
            acc0 = __hmax2(acc0, __hmin2(u2h2(x0), k));
            acc1 = __hmax2(acc1, __hmin2(u2h2(x1), k));
            acc2 = __hmax2(acc2, __hmin2(u2h2(x2), k));
            acc3 = __hmax2(acc3, __hmin2(u2h2(x3), k));
        }
        // ---- kw = 2: cols w0+2..w0+9 = va.y..va.w, ve ----
        {
            uint4 va = *(const uint4*)(xb + r2.y);
            unsigned ve = *(const unsigned*)(xb + r2.y + 16);
            __half2 k = u2h2(r2.x);
            acc0 = __hmax2(acc0, __hmin2(u2h2(va.y), k));
            acc1 = __hmax2(acc1, __hmin2(u2h2(va.z), k));
            acc2 = __hmax2(acc2, __hmin2(u2h2(va.w), k));
            acc3 = __hmax2(acc3, __hmin2(u2h2(ve),   k));
        }
        {
            uint4 va = *(const uint4*)(xb + r2.w);
            unsigned ve = *(const unsigned*)(xb + r2.w + 16);
            __half2 k = u2h2(r2.z);
            acc0 = __hmax2(acc0, __hmin2(u2h2(va.y), k));
            acc1 = __hmax2(acc1, __hmin2(u2h2(va.z), k));
            acc2 = __hmax2(acc2, __hmin2(u2h2(va.w), k));
            acc3 = __hmax2(acc3, __hmin2(u2h2(ve),   k));
        }
    }

    // ---- write 8 w outputs as f32 ----
    int oc = ocbase + ocl;
    float4* o = (float4*)(out + (((size_t)n * OC_ + oc) * H_ + h) * W_ + w0);
    float2 f0 = __half22float2(acc0);
    float2 f1 = __half22float2(acc1);
    float2 f2 = __half22float2(acc2);
    float2 f3 = __half22float2(acc3);
    o[0] = make_float4(f0.x, f0.y, f1.x, f1.y);
    o[1] = make_float4(f2.x, f2.y, f3.x, f3.y);
}

extern "C" void kernel_launch(void* const* d_in, const int* in_sizes, int n_in,
                              void* d_out, int out_size) {
    const float* x = (const float*)d_in[0];
    const float* k = (const float*)d_in[1];
    float* out = (float*)d_out;

    semiconv2d_prep<<<OC_, NTAPS>>>(k);

    size_t smem = (size_t)IC_ * XROWS * XS_STRIDE * sizeof(__half)
                + (size_t)OC_PER_BLK * 3 * LTAPS * sizeof(uint2);  // 66560 + 18432 = 84992 B
    cudaFuncSetAttribute(semiconv2d_rr,
                         cudaFuncAttributeMaxDynamicSharedMemorySize, (int)smem);
    dim3 grid(H_ / TILE_H, OC_ / OC_PER_BLK, N_);                   // 12 x 4 x 8 = 384
    semiconv2d_rr<<<grid, THREADS, smem>>>(x, out);
}